// round 2
// baseline (speedup 1.0000x reference)
#include <cuda_runtime.h>
#include <cstdint>
#include <cstddef>

#define HDIM   128
#define GDIM   512      // 4*H
#define BATCH  256
#define SEQ    512
#define DIN    80
#define EMB    256
#define KSMEM  96       // k-rows of W_hh^T kept in shared memory (rest in registers)

// ---------------- device scratch (no allocations allowed) ----------------
__device__ float g_G[(size_t)BATCH * SEQ * GDIM];   // 268 MB: pre-activation gates (input part)
__device__ float g_hout[(size_t)BATCH * SEQ * HDIM];// 64 MB : per-step h_out
__device__ float g_Wc[GDIM * DIN];                  // fused  W_ih @ W_in   [512][80]
__device__ float g_bc[GDIM];                        // fused  W_ih@b_in + b_ih + b_hh
__device__ float g_WT[HDIM * GDIM];                 // W_hh transposed: WT[k][j] = W_hh[j][k]

// ---------------- math helpers ----------------
__device__ __forceinline__ float sigf(float x) {
    float xc = fminf(fmaxf(x, -30.f), 30.f);
    return __fdividef(1.0f, 1.0f + __expf(-xc));
}
__device__ __forceinline__ float tanh_fast(float x) {
    float xc = fminf(fmaxf(x, -15.f), 15.f);
    float e = __expf(2.0f * xc);
    return 1.0f - __fdividef(2.0f, e + 1.0f);
}

// ---------------- kernel 0: fold W_in into W_ih, transpose W_hh ----------------
__global__ void combine_kernel(const float* __restrict__ W_in, const float* __restrict__ b_in,
                               const float* __restrict__ W_ih, const float* __restrict__ b_ih,
                               const float* __restrict__ W_hh, const float* __restrict__ b_hh) {
    __shared__ float wih[EMB];
    int j = blockIdx.x;           // 0..511
    int tid = threadIdx.x;        // 128 threads
    for (int e = tid; e < EMB; e += 128) wih[e] = W_ih[j * EMB + e];
    // transpose W_hh row j into column j of WT
    g_WT[tid * GDIM + j] = W_hh[j * HDIM + tid];
    __syncthreads();
    if (tid < DIN) {
        float s = 0.f;
        #pragma unroll 8
        for (int e = 0; e < EMB; e++) s = fmaf(wih[e], W_in[e * DIN + tid], s);
        g_Wc[j * DIN + tid] = s;
    }
    if (tid == 96) {
        float s = b_ih[j] + b_hh[j];
        #pragma unroll 8
        for (int e = 0; e < EMB; e++) s = fmaf(wih[e], b_in[e], s);
        g_bc[j] = s;
    }
}

// ---------------- kernel 1: G[m][j] = x[m][:] . Wc[j][:] + bc[j] ----------------
// M = 131072, N = 512, K = 80. BM=BN=128, 256 threads, 8x8 register tile.
__global__ void __launch_bounds__(256) gemm_kernel(const float* __restrict__ x) {
    __shared__ float As[40][132];  // x tile transposed   As[k][m']
    __shared__ float Bs[40][132];  // Wc tile transposed  Bs[k][n']
    __shared__ float bcs[128];

    int tid = threadIdx.x;
    int n0 = blockIdx.x * 128;
    int m0 = blockIdx.y * 128;
    if (tid < 128) bcs[tid] = g_bc[n0 + tid];
    int tr = tid >> 4, tc = tid & 15;

    float acc[8][8];
    #pragma unroll
    for (int i = 0; i < 8; i++)
        #pragma unroll
        for (int jj = 0; jj < 8; jj++) acc[i][jj] = 0.f;

    for (int kt = 0; kt < 2; kt++) {
        #pragma unroll
        for (int r = 0; r < 20; r++) {
            int idx = tid + r * 256;      // 0..5119
            int row = idx / 40;
            int col = idx - row * 40;
            As[col][row] = x[(size_t)(m0 + row) * DIN + kt * 40 + col];
            Bs[col][row] = g_Wc[(n0 + row) * DIN + kt * 40 + col];
        }
        __syncthreads();
        #pragma unroll 2
        for (int k = 0; k < 40; k++) {
            float4 a0 = *(const float4*)&As[k][tr * 8];
            float4 a1 = *(const float4*)&As[k][tr * 8 + 4];
            float4 b0 = *(const float4*)&Bs[k][tc * 8];
            float4 b1 = *(const float4*)&Bs[k][tc * 8 + 4];
            float av[8] = {a0.x, a0.y, a0.z, a0.w, a1.x, a1.y, a1.z, a1.w};
            float bv[8] = {b0.x, b0.y, b0.z, b0.w, b1.x, b1.y, b1.z, b1.w};
            #pragma unroll
            for (int i = 0; i < 8; i++)
                #pragma unroll
                for (int jj = 0; jj < 8; jj++)
                    acc[i][jj] = fmaf(av[i], bv[jj], acc[i][jj]);
        }
        __syncthreads();
    }

    #pragma unroll
    for (int i = 0; i < 8; i++) {
        float* orow = g_G + (size_t)(m0 + tr * 8 + i) * GDIM + n0 + tc * 8;
        float4 v0 = make_float4(acc[i][0] + bcs[tc * 8 + 0], acc[i][1] + bcs[tc * 8 + 1],
                                acc[i][2] + bcs[tc * 8 + 2], acc[i][3] + bcs[tc * 8 + 3]);
        float4 v1 = make_float4(acc[i][4] + bcs[tc * 8 + 4], acc[i][5] + bcs[tc * 8 + 5],
                                acc[i][6] + bcs[tc * 8 + 6], acc[i][7] + bcs[tc * 8 + 7]);
        *(float4*)orow = v0;
        *(float4*)(orow + 4) = v1;
    }
}

// ---------------- kernel 2: sequential LSTM recurrence + time pooling ----------------
// 128 blocks x 512 threads; block owns batch rows (2b, 2b+1) for all 512 steps.
// W_hh^T: rows [0,96) in smem, rows [96,128) register-resident per thread (column tid).
__global__ void __launch_bounds__(512, 1) lstm_kernel(const float* __restrict__ w_time) {
    extern __shared__ float smem[];
    float* gates = smem;                 // [2][512]
    float* hbuf  = smem + 1024;          // interleaved (h_b0, h_b1) pairs: 128 float2
    float* WTs   = smem + 1280;          // [KSMEM][512]

    int tid = threadIdx.x;
    int b0 = blockIdx.x * 2;

    for (int i = tid; i < KSMEM * GDIM; i += 512) WTs[i] = g_WT[i];
    float wreg[HDIM - KSMEM];
    #pragma unroll
    for (int i = 0; i < HDIM - KSMEM; i++) wreg[i] = g_WT[(KSMEM + i) * GDIM + tid];
    if (tid < 256) hbuf[tid] = 0.f;

    float wt0 = w_time[0], wt1 = w_time[1], wt2 = w_time[2];
    float cc = 0.f, hs0 = 0.f, hs1 = 0.f, cs0 = 0.f, cs1 = 0.f;
    __syncthreads();

    const float* G0 = g_G + (size_t)b0 * SEQ * GDIM + tid;
    const float* G1 = g_G + (size_t)(b0 + 1) * SEQ * GDIM + tid;
    float* hout0 = g_hout + (size_t)b0 * SEQ * HDIM;
    float* hout1 = g_hout + (size_t)(b0 + 1) * SEQ * HDIM;

    int slot = 0;
    for (int t = 0; t < SEQ; t++) {
        float gin0 = G0[(size_t)t * GDIM];
        float gin1 = G1[(size_t)t * GDIM];
        float acc0 = gin0, acc1 = gin1;
        const float4* hp4 = (const float4*)hbuf;   // hp4[k/2] = (h0[k],h1[k],h0[k+1],h1[k+1])
        #pragma unroll
        for (int k = 0; k < KSMEM; k += 2) {
            float4 h4 = hp4[k >> 1];
            float wa = WTs[k * GDIM + tid];
            float wb = WTs[(k + 1) * GDIM + tid];
            acc0 = fmaf(wa, h4.x, acc0);
            acc1 = fmaf(wa, h4.y, acc1);
            acc0 = fmaf(wb, h4.z, acc0);
            acc1 = fmaf(wb, h4.w, acc1);
        }
        #pragma unroll
        for (int i = 0; i < HDIM - KSMEM; i += 2) {
            float4 h4 = hp4[(KSMEM + i) >> 1];
            acc0 = fmaf(wreg[i], h4.x, acc0);
            acc1 = fmaf(wreg[i], h4.y, acc1);
            acc0 = fmaf(wreg[i + 1], h4.z, acc0);
            acc1 = fmaf(wreg[i + 1], h4.w, acc1);
        }
        gates[tid] = acc0;
        gates[GDIM + tid] = acc1;
        __syncthreads();

        if (tid < 256) {
            int b = tid >> 7, k = tid & 127;
            const float* gb = gates + b * GDIM;
            float ig = gb[k], fg = gb[HDIM + k], gg = gb[2 * HDIM + k], og = gb[3 * HDIM + k];
            float cn = fmaf(sigf(fg), cc, sigf(ig) * tanh_fast(gg));
            float hn = sigf(og) * tanh_fast(cn);
            float ho, co;
            if (slot == 0)      { hs0 = hn; cs0 = cn; ho = hn; co = cn; }
            else if (slot == 1) { hs1 = hn; cs1 = cn; ho = hn; co = cn; }
            else {
                ho = wt0 * hs0 + wt1 * hs1 + wt2 * hn;
                co = wt0 * cs0 + wt1 * cs1 + wt2 * cn;
            }
            cc = co;
            hbuf[2 * k + b] = ho;
            (b ? hout1 : hout0)[(size_t)t * HDIM + k] = ho;
        }
        slot = (slot == 2) ? 0 : slot + 1;
        __syncthreads();
    }
}

// ---------------- kernel 3: logits = hout @ W_br^T + b_br, then log_softmax ----------------
// one warp per (b,s) row; 8 warps per block.
__global__ void __launch_bounds__(256) logits_kernel(const float* __restrict__ W_br,
                                                     const float* __restrict__ b_br,
                                                     float* __restrict__ out) {
    __shared__ float wbr[4 * HDIM];
    __shared__ float bb[4];
    int tid = threadIdx.x;
    for (int i = tid; i < 4 * HDIM; i += 256) wbr[i] = W_br[i];
    if (tid < 4) bb[tid] = b_br[tid];
    __syncthreads();

    int warp = tid >> 5, lane = tid & 31;
    size_t row = (size_t)blockIdx.x * 8 + warp;
    const float* h = g_hout + row * HDIM;

    float p0 = 0.f, p1 = 0.f, p2 = 0.f, p3 = 0.f;
    #pragma unroll
    for (int k = lane; k < HDIM; k += 32) {
        float hv = h[k];
        p0 = fmaf(hv, wbr[k], p0);
        p1 = fmaf(hv, wbr[HDIM + k], p1);
        p2 = fmaf(hv, wbr[2 * HDIM + k], p2);
        p3 = fmaf(hv, wbr[3 * HDIM + k], p3);
    }
    #pragma unroll
    for (int off = 16; off; off >>= 1) {
        p0 += __shfl_down_sync(0xffffffffu, p0, off);
        p1 += __shfl_down_sync(0xffffffffu, p1, off);
        p2 += __shfl_down_sync(0xffffffffu, p2, off);
        p3 += __shfl_down_sync(0xffffffffu, p3, off);
    }
    if (lane == 0) {
        float x0 = p0 + bb[0], x1 = p1 + bb[1], x2 = p2 + bb[2], x3 = p3 + bb[3];
        float m = fmaxf(fmaxf(x0, x1), fmaxf(x2, x3));
        float s = __expf(x0 - m) + __expf(x1 - m) + __expf(x2 - m) + __expf(x3 - m);
        float l = __logf(s);
        float4 o = make_float4(x0 - m - l, x1 - m - l, x2 - m - l, x3 - m - l);
        *(float4*)(out + row * 4) = o;
    }
}

// ---------------- launch ----------------
extern "C" void kernel_launch(void* const* d_in, const int* in_sizes, int n_in,
                              void* d_out, int out_size) {
    const float* x      = (const float*)d_in[0];
    const float* W_in   = (const float*)d_in[1];
    const float* b_in   = (const float*)d_in[2];
    const float* W_ih   = (const float*)d_in[3];
    const float* b_ih   = (const float*)d_in[4];
    const float* W_hh   = (const float*)d_in[5];
    const float* b_hh   = (const float*)d_in[6];
    const float* w_time = (const float*)d_in[7];
    const float* W_br   = (const float*)d_in[8];
    const float* b_br   = (const float*)d_in[9];
    float* out = (float*)d_out;

    combine_kernel<<<GDIM, 128>>>(W_in, b_in, W_ih, b_ih, W_hh, b_hh);
    gemm_kernel<<<dim3(4, 1024), 256>>>(x);

    size_t shmem = (size_t)(1024 + 256 + KSMEM * GDIM) * sizeof(float);  // 201728 B
    cudaFuncSetAttribute(lstm_kernel, cudaFuncAttributeMaxDynamicSharedMemorySize, (int)shmem);
    lstm_kernel<<<BATCH / 2, 512, shmem>>>(w_time);

    logits_kernel<<<(BATCH * SEQ) / 8, 256>>>(W_br, b_br, out);
}